// round 6
// baseline (speedup 1.0000x reference)
#include <cuda_runtime.h>
#include <cstdint>

// Temporal_Attention — weight-space-collapsed, 5 wide short-chain kernels.
// B=64, T=256, D=128, H=8, E=128.  out[B,D] fp32.
//
//  k_pre : G'[h,dp,d], ub', gb', dq', M, cbias, xs[b], S
//  k_u   : u[b,h,d] = xs[b].G'[h,:,d] + S ub'   (G smem-tiled, read once-ish)
//  k_sum : scores[b,h,t] = x[b,t].u[b,h] + c[b,h]; per-quarter (max,sumexp)
//  k_y   : beta from scores+global stats; y_q[b,q,h,d] partials
//  k_out : y combine; out = y @ M + cbias  (4 batches per CTA -> M traffic /4)

#define BB 64
#define TT 256
#define DD 128
#define HH 8
#define HE 1024
#define SCALE 0.088388347648318447f

static __device__ float g_S;
static __device__ __align__(16) float g_xs[BB * DD];
static __device__ __align__(16) float g_G[HH * DD * DD];
static __device__ __align__(16) float g_ub[HH * DD];
static __device__ __align__(16) float g_gb[HH * DD];
static __device__ float g_dqs[HH];
static __device__ __align__(16) float g_M[HE * DD];
static __device__ __align__(16) float g_cbp[8 * DD];
static __device__ __align__(16) float g_u[BB * HE];
static __device__ __align__(16) float g_sc[BB * HH * TT];   // raw scores [b][h][t]
static __device__ __align__(8)  float2 g_stat[BB * 4 * HH]; // [b][q][h] = (max, sumexp)
static __device__ __align__(16) float g_yq[BB * 4 * HE];    // y partials [b][q][k]

// ---- helpers ---------------------------------------------------------------
__device__ __forceinline__ void ffma2(unsigned long long& d,
                                      unsigned long long a, unsigned long long b) {
    asm("fma.rn.f32x2 %0, %1, %2, %0;" : "+l"(d) : "l"(a), "l"(b));
}
__device__ __forceinline__ unsigned long long pk2(float x, float y) {
    unsigned long long r;
    asm("mov.b64 %0, {%1, %2};" : "=l"(r) : "f"(x), "f"(y));
    return r;
}
__device__ __forceinline__ float2 upk2(unsigned long long v) {
    float lo, hi;
    asm("mov.b64 {%0, %1}, %2;" : "=f"(lo), "=f"(hi) : "l"(v));
    return make_float2(lo, hi);
}
__device__ __forceinline__ float dot4(float4 a, float4 b) {
    return a.x * b.x + a.y * b.y + a.z * b.z + a.w * b.w;
}

// ===========================================================================
// K1: grid 209 x 256.  roles: xs(0-63) | G(64-127) | M(128-191) | gb(192-199)
//                             | cbias(200-207) | misc(208)
__global__ __launch_bounds__(256) void k_pre(
    const float* __restrict__ x,  const float* __restrict__ Ws,
    const float* __restrict__ Wk, const float* __restrict__ bk,
    const float* __restrict__ Wq, const float* __restrict__ bq,
    const float* __restrict__ Wv, const float* __restrict__ bv,
    const float* __restrict__ Wo, const float* __restrict__ bo)
{
    __shared__ __align__(16) float s[12288];   // 48 KB
    const int blk = blockIdx.x, tid = threadIdx.x;

    if (blk < 64) {
        // ------------- xs role: one batch -------------
        const int b = blk, c = tid & 31, tg = tid >> 5;
        const float4* x4 = (const float4*)x;
        float4 acc = make_float4(0.f, 0.f, 0.f, 0.f);
        #pragma unroll 16
        for (int t = tg * 32; t < tg * 32 + 32; t++) {
            float w = __ldg(Ws + t);
            float4 xv = x4[(b * TT + t) * 32 + c];
            acc.x += w * xv.x; acc.y += w * xv.y;
            acc.z += w * xv.z; acc.w += w * xv.w;
        }
        float4* p4 = (float4*)s;
        p4[tg * 32 + c] = acc;
        __syncthreads();
        if (tid < 32) {
            float4 r = p4[tid];
            #pragma unroll
            for (int g = 1; g < 8; g++) {
                float4 v = p4[g * 32 + tid];
                r.x += v.x; r.y += v.y; r.z += v.z; r.w += v.w;
            }
            ((float4*)g_xs)[b * 32 + tid] = r;
        }
    } else if (blk < 128) {
        // ------------- G role: G'[h, r0..r0+15, :] (+ub on rt==0) -------------
        const int w = blk - 64, h = w >> 3, rt = w & 7, r0 = rt * 16;
        const int d2 = tid & 127, rg = tid >> 7;
        float4* wq4s = (float4*)s;            // [128][17] float4
        float4* wk4s = (float4*)(s + 8704);   // [16][16]
        float4* bk4s = (float4*)(s + 9728);   // [16]
        const float4* Wq4 = (const float4*)Wq;
        const float4* Wk4 = (const float4*)Wk;
        float acc[8];
        #pragma unroll
        for (int j = 0; j < 8; j++) acc[j] = 0.f;
        float ubacc = 0.f;
        for (int e0 = 0; e0 < 2; e0++) {           // e-chunks of 64
            #pragma unroll
            for (int k = 0; k < 8; k++) {
                int i = tid + k * 256;
                int dd = i >> 4, eq = i & 15;
                wq4s[dd * 17 + eq] = Wq4[dd * 256 + h * 32 + e0 * 16 + eq];
            }
            {
                int r = tid >> 4, eq = tid & 15;
                wk4s[r * 16 + eq] = Wk4[(r0 + r) * 256 + h * 32 + e0 * 16 + eq];
            }
            if (rt == 0 && tid < 16)
                bk4s[tid] = ((const float4*)bk)[h * 32 + e0 * 16 + tid];
            __syncthreads();
            #pragma unroll 4
            for (int e4 = 0; e4 < 16; e4++) {
                float4 q4 = wq4s[d2 * 17 + e4];
                #pragma unroll
                for (int j = 0; j < 8; j++)
                    acc[j] += dot4(q4, wk4s[(rg * 8 + j) * 16 + e4]);
                if (rt == 0 && rg == 0) ubacc += dot4(q4, bk4s[e4]);
            }
            __syncthreads();
        }
        #pragma unroll
        for (int j = 0; j < 8; j++)
            g_G[h * 16384 + (r0 + rg * 8 + j) * DD + d2] = SCALE * acc[j];
        if (rt == 0 && rg == 0) g_ub[h * DD + d2] = SCALE * ubacc;
    } else if (blk < 192) {
        // ------------- M role: M[h, r0..r0+15, :] -------------
        const int w = blk - 128, h = w >> 3, r0 = (w & 7) * 16;
        const int d2 = tid & 127, rh = tid >> 7;
        float* wo_s = s;            // 64 x 128
        float* wv_s = s + 8192;     // 16 x 64
        float acc[8];
        #pragma unroll
        for (int j = 0; j < 8; j++) acc[j] = 0.f;
        for (int e0 = 0; e0 < 128; e0 += 64) {
            for (int i = tid; i < 8192; i += 256) {
                int e = i >> 7, dd = i & 127;
                wo_s[i] = Wo[(h * 128 + e0 + e) * DD + dd];
            }
            for (int i = tid; i < 1024; i += 256) {
                int r = i >> 6, e = i & 63;
                wv_s[i] = Wv[(r0 + r) * HE + h * 128 + e0 + e];
            }
            __syncthreads();
            #pragma unroll 8
            for (int e = 0; e < 64; e++) {
                float wo = wo_s[e * 128 + d2];
                #pragma unroll
                for (int j = 0; j < 8; j++)
                    acc[j] += wv_s[(rh * 8 + j) * 64 + e] * wo;
            }
            __syncthreads();
        }
        #pragma unroll
        for (int j = 0; j < 8; j++)
            g_M[(h * 128 + r0 + rh * 8 + j) * DD + d2] = acc[j];
    } else if (blk < 200) {
        // ------------- gb role: gb'[h, :] -------------
        const int h = blk - 192, eq = tid & 31, dg = tid >> 5;
        float4 bqv = ((const float4*)bq)[h * 32 + eq];
        const float4* Wk4 = (const float4*)Wk;
        #pragma unroll
        for (int i = 0; i < 16; i++) {
            int dd = dg * 16 + i;
            float p = dot4(Wk4[dd * 256 + h * 32 + eq], bqv);
            #pragma unroll
            for (int o = 16; o > 0; o >>= 1)
                p += __shfl_xor_sync(0xffffffffu, p, o);
            if (eq == 0) g_gb[h * DD + dd] = SCALE * p;
        }
    } else if (blk < 208) {
        // ------------- cbias partial: k-slice p -------------
        const int p = blk - 200, d2 = tid & 127, kh = tid >> 7;
        float acc = 0.f;
        #pragma unroll 8
        for (int i = 0; i < 64; i++) {
            int k = p * 128 + kh * 64 + i;
            acc += __ldg(bv + k) * Wo[k * DD + d2];
        }
        s[tid] = acc;
        __syncthreads();
        if (kh == 0)
            g_cbp[p * DD + d2] = s[d2] + s[128 + d2] + (p == 0 ? bo[d2] : 0.f);
    } else {
        // ------------- misc: S, dq' -------------
        s[tid] = Ws[tid];
        {
            int h = tid >> 5, lane = tid & 31;
            float p = dot4(((const float4*)bk)[h * 32 + lane],
                           ((const float4*)bq)[h * 32 + lane]);
            #pragma unroll
            for (int o = 16; o > 0; o >>= 1)
                p += __shfl_xor_sync(0xffffffffu, p, o);
            if (lane == 0) g_dqs[h] = SCALE * p;
        }
        __syncthreads();
        for (int st = 128; st > 0; st >>= 1) {
            if (tid < st) s[tid] += s[tid + st];
            __syncthreads();
        }
        if (tid == 0) g_S = s[0];
    }
}

// ===========================================================================
// K2: u[b,h,d] = xs[b].G'[h,:,d] + S ub'.  grid 64 = (h, d-tile of 16), 256 thr.
// G read once total via smem tiles (1.5 MB aggregate L2 traffic).
__global__ __launch_bounds__(256) void k_u(void) {
    __shared__ __align__(16) float xs_s[64 * 133];   // 34.0 KB (pad 133, gcd(133,32)=1... 133 mod 32 = 5 ok)
    __shared__ __align__(16) float G_s[128 * 20];    // 10.2 KB (pad 20 for f4 align)
    const int h = blockIdx.x >> 3, dt = blockIdx.x & 7;
    const int tid = threadIdx.x;

    #pragma unroll
    for (int k = 0; k < 32; k++) {
        int i = tid + k * 256;
        xs_s[(i >> 7) * 133 + (i & 127)] = g_xs[i];
    }
    #pragma unroll
    for (int k = 0; k < 8; k++) {
        int i = tid + k * 256;
        int dp = i >> 4, j = i & 15;
        G_s[dp * 20 + j] = g_G[h * 16384 + dp * 128 + dt * 16 + j];
    }
    __syncthreads();

    const int b = tid >> 2, dq = tid & 3;
    float S = g_S;
    float4 acc = ((const float4*)g_ub)[h * 32 + dt * 4 + dq];
    acc.x *= S; acc.y *= S; acc.z *= S; acc.w *= S;
    const float* xr = xs_s + b * 133;
    #pragma unroll 8
    for (int dp = 0; dp < 128; dp++) {
        float xv = xr[dp];
        float4 g4 = *(const float4*)(G_s + dp * 20 + dq * 4);
        acc.x += xv * g4.x; acc.y += xv * g4.y;
        acc.z += xv * g4.z; acc.w += xv * g4.w;
    }
    ((float4*)g_u)[b * 256 + h * 32 + dt * 4 + dq] = acc;
}

// ===========================================================================
// K3: scores + per-quarter softmax stats.  grid 256 = (b, t-quarter), 256 thr.
__global__ __launch_bounds__(256) void k_sum(
    const float* __restrict__ x, const float* __restrict__ bs)
{
    __shared__ __align__(16) float sxT[128 * 65];   // 33.3 KB
    __shared__ __align__(16) float su_s[1024];      // u[d][h]
    __shared__ __align__(16) float scomb[512];      // [h][t_local]
    __shared__ float sc[8];
    const int b = blockIdx.x >> 2, q = blockIdx.x & 3;
    const int tid = threadIdx.x;

    // u -> smem transposed [d][8h]
    #pragma unroll
    for (int k = 0; k < 4; k++) {
        int i = tid + k * 256;
        su_s[(i & 127) * 8 + (i >> 7)] = g_u[b * HE + i];
    }
    // c[b,h]: warp per head
    {
        int hh = tid >> 5, lane = tid & 31;
        float p = dot4(((const float4*)g_xs)[b * 32 + lane],
                       ((const float4*)g_gb)[hh * 32 + lane]);
        #pragma unroll
        for (int o = 16; o > 0; o >>= 1)
            p += __shfl_xor_sync(0xffffffffu, p, o);
        if (lane == 0) sc[hh] = p + g_S * g_dqs[hh] + bs[0];
    }
    // x quarter-tile, transposed
    {
        const int d = tid & 127, tg = tid >> 7;
        const float* xb = x + ((size_t)(b * TT + q * 64)) * DD + d;
        #pragma unroll
        for (int k = 0; k < 32; k++) {
            int t = k * 2 + tg;
            sxT[d * 65 + t] = xb[t * DD];
        }
    }
    __syncthreads();

    // summary: thread (t, h-pair)
    {
        const int t = tid & 63, hp = tid >> 6;
        unsigned long long acc = 0ull;
        const unsigned long long* su2 = (const unsigned long long*)su_s;
        #pragma unroll 16
        for (int d = 0; d < 128; d++) {
            float xv = sxT[d * 65 + t];
            ffma2(acc, su2[d * 4 + hp], pk2(xv, xv));
        }
        float2 v = upk2(acc);
        scomb[(hp * 2)     * 64 + t] = v.x + sc[hp * 2];
        scomb[(hp * 2 + 1) * 64 + t] = v.y + sc[hp * 2 + 1];
    }
    __syncthreads();

    // per-quarter stats: warp per head
    {
        int hh = tid >> 5, lane = tid & 31;
        float v0 = scomb[hh * 64 + lane];
        float v1 = scomb[hh * 64 + 32 + lane];
        float m = fmaxf(v0, v1);
        #pragma unroll
        for (int o = 16; o > 0; o >>= 1)
            m = fmaxf(m, __shfl_xor_sync(0xffffffffu, m, o));
        float ssum = __expf(v0 - m) + __expf(v1 - m);
        #pragma unroll
        for (int o = 16; o > 0; o >>= 1)
            ssum += __shfl_xor_sync(0xffffffffu, ssum, o);
        if (lane == 0) g_stat[(b * 4 + q) * 8 + hh] = make_float2(m, ssum);
    }
    // raw scores -> gmem
    #pragma unroll
    for (int k = 0; k < 2; k++) {
        int i = tid + k * 256;
        g_sc[(b * 8 + (i >> 6)) * TT + q * 64 + (i & 63)] = scomb[i];
    }
}

// ===========================================================================
// K4: beta + y quarter-partials.  grid 256 = (b, q), 256 thr.
__global__ __launch_bounds__(256) void k_y(const float* __restrict__ x)
{
    __shared__ __align__(16) float sxT[128 * 65];   // 33.3 KB
    __shared__ __align__(16) float sbeta[512];      // [t][h]
    __shared__ __align__(16) float spart[2048];
    __shared__ float smx[8], sinv[8];
    const int b = blockIdx.x >> 2, q = blockIdx.x & 3;
    const int tid = threadIdx.x;

    // global softmax stats
    if (tid < 8) {
        float2 st0 = g_stat[(b * 4 + 0) * 8 + tid];
        float2 st1 = g_stat[(b * 4 + 1) * 8 + tid];
        float2 st2 = g_stat[(b * 4 + 2) * 8 + tid];
        float2 st3 = g_stat[(b * 4 + 3) * 8 + tid];
        float m = fmaxf(fmaxf(st0.x, st1.x), fmaxf(st2.x, st3.x));
        float denom = st0.y * __expf(st0.x - m) + st1.y * __expf(st1.x - m)
                    + st2.y * __expf(st2.x - m) + st3.y * __expf(st3.x - m);
        smx[tid] = m;
        sinv[tid] = 1.f / denom;
    }
    // x quarter-tile, transposed
    {
        const int d = tid & 127, tg = tid >> 7;
        const float* xb = x + ((size_t)(b * TT + q * 64)) * DD + d;
        #pragma unroll
        for (int k = 0; k < 32; k++) {
            int t = k * 2 + tg;
            sxT[d * 65 + t] = xb[t * DD];
        }
    }
    __syncthreads();

    // beta[t][h]
    #pragma unroll
    for (int k = 0; k < 2; k++) {
        int i = tid + k * 256;
        int hh = i >> 6, t = i & 63;
        float v = g_sc[(b * 8 + hh) * TT + q * 64 + t];
        sbeta[t * 8 + hh] = __expf(v - smx[hh]) * sinv[hh];
    }
    __syncthreads();

    // y partials: thread (d, t-half)
    {
        const int d = tid & 127, tg = tid >> 7;
        unsigned long long a0 = 0, a1 = 0, a2 = 0, a3 = 0;
        #pragma unroll 8
        for (int t = tg * 32; t < tg * 32 + 32; t++) {
            float xv = sxT[d * 65 + t];
            unsigned long long xp = pk2(xv, xv);
            const ulonglong2* bp = (const ulonglong2*)(sbeta + t * 8);
            ulonglong2 b01 = bp[0], b23 = bp[1];
            ffma2(a0, b01.x, xp); ffma2(a1, b01.y, xp);
            ffma2(a2, b23.x, xp); ffma2(a3, b23.y, xp);
        }
        float2 v0 = upk2(a0), v1 = upk2(a1), v2 = upk2(a2), v3 = upk2(a3);
        float* pg = spart + tg * 1024;
        pg[0 * 128 + d] = v0.x; pg[1 * 128 + d] = v0.y;
        pg[2 * 128 + d] = v1.x; pg[3 * 128 + d] = v1.y;
        pg[4 * 128 + d] = v2.x; pg[5 * 128 + d] = v2.y;
        pg[6 * 128 + d] = v3.x; pg[7 * 128 + d] = v3.y;
    }
    __syncthreads();
    #pragma unroll
    for (int k = 0; k < 4; k++) {
        int i = tid + k * 256;
        g_yq[(b * 4 + q) * HE + i] = spart[i] + spart[1024 + i];
    }
}

// ===========================================================================
// K5: y combine + out = y @ M + cbias.  grid 64 = (b-quad, d2-tile of 32), 256 thr.
// 4 batches per CTA -> M read 16x total-batches/4 = 8 MB aggregate.
__global__ __launch_bounds__(256) void k_out(float* __restrict__ out)
{
    __shared__ __align__(16) float sy[4 * HE];      // 16 KB
    __shared__ __align__(16) float sp[8 * 4 * 32];  // 4 KB
    const int bqd = blockIdx.x;
    const int b0 = (bqd >> 2) * 4, dt = bqd & 3;
    const int tid = threadIdx.x;

    #pragma unroll
    for (int k = 0; k < 16; k++) {
        int i = tid + k * 256;
        int bb = i >> 10, kk = i & 1023;
        const float* yp = g_yq + ((size_t)(b0 + bb) * 4) * HE + kk;
        sy[i] = yp[0] + yp[HE] + yp[2 * HE] + yp[3 * HE];
    }
    __syncthreads();

    {
        const int d2 = tid & 31, kg = tid >> 5;
        const float* Mp = g_M + dt * 32 + d2;
        float a0 = 0.f, a1 = 0.f, a2 = 0.f, a3 = 0.f;
        #pragma unroll 8
        for (int k = kg * 128; k < kg * 128 + 128; k++) {
            float mv = __ldg(Mp + k * 128);
            a0 += sy[k] * mv;
            a1 += sy[HE + k] * mv;
            a2 += sy[2 * HE + k] * mv;
            a3 += sy[3 * HE + k] * mv;
        }
        sp[(kg * 4 + 0) * 32 + d2] = a0;
        sp[(kg * 4 + 1) * 32 + d2] = a1;
        sp[(kg * 4 + 2) * 32 + d2] = a2;
        sp[(kg * 4 + 3) * 32 + d2] = a3;
    }
    __syncthreads();
    if (tid < 128) {
        int bb = tid >> 5, d = tid & 31;
        float o = 0.f;
        #pragma unroll
        for (int p = 0; p < 8; p++) o += g_cbp[p * DD + dt * 32 + d];
        #pragma unroll
        for (int kg = 0; kg < 8; kg++) o += sp[(kg * 4 + bb) * 32 + d];
        out[(b0 + bb) * DD + dt * 32 + d] = o;
    }
}

// ===========================================================================
extern "C" void kernel_launch(void* const* d_in, const int* in_sizes, int n_in,
                              void* d_out, int out_size) {
    const float* x  = (const float*)d_in[0];
    const float* Wq = (const float*)d_in[1];
    const float* bq = (const float*)d_in[2];
    const float* Wk = (const float*)d_in[3];
    const float* bk = (const float*)d_in[4];
    const float* Wv = (const float*)d_in[5];
    const float* bv = (const float*)d_in[6];
    const float* Ws = (const float*)d_in[7];
    const float* bs = (const float*)d_in[8];
    const float* Wo = (const float*)d_in[9];
    const float* bo = (const float*)d_in[10];
    float* out = (float*)d_out;

    k_pre<<<209, 256>>>(x, Ws, Wk, bk, Wq, bq, Wv, bv, Wo, bo);
    k_u<<<64, 256>>>();
    k_sum<<<256, 256>>>(x, bs);
    k_y<<<256, 256>>>(x);
    k_out<<<64, 256>>>(out);
}

// round 7
// speedup vs baseline: 1.6337x; 1.6337x over previous
#include <cuda_runtime.h>
#include <cstdint>

// Temporal_Attention — weight-space-collapsed.
// k_pre: weight-only precompute (G', ub', gb', dq', M, cbias, S).
// k_main: per-batch cluster of 4 CTAs (t-quarters); xs, u, summary, softmax,
//         y, out all fused with DSMEM exchanges. grid 256 x 256 thr.
// B=64, T=256, D=128, H=8, E=128.  out[B,D] fp32.

#define BB 64
#define TT 256
#define DD 128
#define HH 8
#define HE 1024
#define SCALE 0.088388347648318447f

static __device__ float g_S;
static __device__ __align__(16) float g_G[HH * DD * DD];   // [h][dp][d]
static __device__ __align__(16) float g_ub[HH * DD];
static __device__ __align__(16) float g_gb[HH * DD];
static __device__ float g_dqs[HH];
static __device__ __align__(16) float g_M[HE * DD];        // [k][d2]
static __device__ __align__(16) float g_cbp[8 * DD];

// ---- helpers ---------------------------------------------------------------
__device__ __forceinline__ void ffma2(unsigned long long& d,
                                      unsigned long long a, unsigned long long b) {
    asm("fma.rn.f32x2 %0, %1, %2, %0;" : "+l"(d) : "l"(a), "l"(b));
}
__device__ __forceinline__ unsigned long long pk2(float x, float y) {
    unsigned long long r;
    asm("mov.b64 %0, {%1, %2};" : "=l"(r) : "f"(x), "f"(y));
    return r;
}
__device__ __forceinline__ float2 upk2(unsigned long long v) {
    float lo, hi;
    asm("mov.b64 {%0, %1}, %2;" : "=f"(lo), "=f"(hi) : "l"(v));
    return make_float2(lo, hi);
}
__device__ __forceinline__ float dot4(float4 a, float4 b) {
    return a.x * b.x + a.y * b.y + a.z * b.z + a.w * b.w;
}
__device__ __forceinline__ uint32_t smem_u32(const void* p) {
    uint32_t a;
    asm("{ .reg .u64 t; cvta.to.shared.u64 t, %1; cvt.u32.u64 %0, t; }"
        : "=r"(a) : "l"(p));
    return a;
}
__device__ __forceinline__ uint32_t mapa_rank(uint32_t addr, uint32_t rank) {
    uint32_t r;
    asm("mapa.shared::cluster.u32 %0, %1, %2;" : "=r"(r) : "r"(addr), "r"(rank));
    return r;
}
__device__ __forceinline__ float ld_dsmem(uint32_t a) {
    float v;
    asm volatile("ld.shared::cluster.f32 %0, [%1];" : "=f"(v) : "r"(a));
    return v;
}
#define CLUSTER_SYNC() do { \
    asm volatile("barrier.cluster.arrive.aligned;" ::: "memory"); \
    asm volatile("barrier.cluster.wait.aligned;" ::: "memory"); \
} while (0)

// ===========================================================================
// K1: grid 145 x 256.  roles: G(0-63) | M(64-127) | gb(128-135)
//                             | cbias(136-143) | misc(144)
__global__ __launch_bounds__(256) void k_pre(
    const float* __restrict__ Ws,
    const float* __restrict__ Wk, const float* __restrict__ bk,
    const float* __restrict__ Wq, const float* __restrict__ bq,
    const float* __restrict__ Wv, const float* __restrict__ bv,
    const float* __restrict__ Wo, const float* __restrict__ bo)
{
    __shared__ __align__(16) float s[12288];   // 48 KB
    const int blk = blockIdx.x, tid = threadIdx.x;

    if (blk < 64) {
        // ------------- G role: G'[h, r0..r0+15, :] (+ub on rt==0) -------------
        const int w = blk, h = w >> 3, rt = w & 7, r0 = rt * 16;
        const int d2 = tid & 127, rg = tid >> 7;
        float4* wq4s = (float4*)s;            // [128][17] float4
        float4* wk4s = (float4*)(s + 8704);   // [16][16]
        float4* bk4s = (float4*)(s + 9728);   // [16]
        const float4* Wq4 = (const float4*)Wq;
        const float4* Wk4 = (const float4*)Wk;
        float acc[8];
        #pragma unroll
        for (int j = 0; j < 8; j++) acc[j] = 0.f;
        float ubacc = 0.f;
        for (int e0 = 0; e0 < 2; e0++) {           // e-chunks of 64
            #pragma unroll
            for (int k = 0; k < 8; k++) {
                int i = tid + k * 256;
                int dd = i >> 4, eq = i & 15;
                wq4s[dd * 17 + eq] = Wq4[dd * 256 + h * 32 + e0 * 16 + eq];
            }
            {
                int r = tid >> 4, eq = tid & 15;
                wk4s[r * 16 + eq] = Wk4[(r0 + r) * 256 + h * 32 + e0 * 16 + eq];
            }
            if (rt == 0 && tid < 16)
                bk4s[tid] = ((const float4*)bk)[h * 32 + e0 * 16 + tid];
            __syncthreads();
            #pragma unroll 4
            for (int e4 = 0; e4 < 16; e4++) {
                float4 q4 = wq4s[d2 * 17 + e4];
                #pragma unroll
                for (int j = 0; j < 8; j++)
                    acc[j] += dot4(q4, wk4s[(rg * 8 + j) * 16 + e4]);
                if (rt == 0 && rg == 0) ubacc += dot4(q4, bk4s[e4]);
            }
            __syncthreads();
        }
        #pragma unroll
        for (int j = 0; j < 8; j++)
            g_G[h * 16384 + (r0 + rg * 8 + j) * DD + d2] = SCALE * acc[j];
        if (rt == 0 && rg == 0) g_ub[h * DD + d2] = SCALE * ubacc;
    } else if (blk < 128) {
        // ------------- M role: M[h, r0..r0+15, :] -------------
        const int w = blk - 64, h = w >> 3, r0 = (w & 7) * 16;
        const int d2 = tid & 127, rh = tid >> 7;
        float* wo_s = s;            // 64 x 128
        float* wv_s = s + 8192;     // 16 x 64
        float acc[8];
        #pragma unroll
        for (int j = 0; j < 8; j++) acc[j] = 0.f;
        for (int e0 = 0; e0 < 128; e0 += 64) {
            for (int i = tid; i < 8192; i += 256) {
                int e = i >> 7, dd = i & 127;
                wo_s[i] = Wo[(h * 128 + e0 + e) * DD + dd];
            }
            for (int i = tid; i < 1024; i += 256) {
                int r = i >> 6, e = i & 63;
                wv_s[i] = Wv[(r0 + r) * HE + h * 128 + e0 + e];
            }
            __syncthreads();
            #pragma unroll 8
            for (int e = 0; e < 64; e++) {
                float wo = wo_s[e * 128 + d2];
                #pragma unroll
                for (int j = 0; j < 8; j++)
                    acc[j] += wv_s[(rh * 8 + j) * 64 + e] * wo;
            }
            __syncthreads();
        }
        #pragma unroll
        for (int j = 0; j < 8; j++)
            g_M[(h * 128 + r0 + rh * 8 + j) * DD + d2] = acc[j];
    } else if (blk < 136) {
        // ------------- gb role: gb'[h, :] -------------
        const int h = blk - 128, eq = tid & 31, dg = tid >> 5;
        float4 bqv = ((const float4*)bq)[h * 32 + eq];
        const float4* Wk4 = (const float4*)Wk;
        #pragma unroll
        for (int i = 0; i < 16; i++) {
            int dd = dg * 16 + i;
            float p = dot4(Wk4[dd * 256 + h * 32 + eq], bqv);
            #pragma unroll
            for (int o = 16; o > 0; o >>= 1)
                p += __shfl_xor_sync(0xffffffffu, p, o);
            if (eq == 0) g_gb[h * DD + dd] = SCALE * p;
        }
    } else if (blk < 144) {
        // ------------- cbias partial: k-slice p -------------
        const int p = blk - 136, d2 = tid & 127, kh = tid >> 7;
        float acc = 0.f;
        #pragma unroll 8
        for (int i = 0; i < 64; i++) {
            int k = p * 128 + kh * 64 + i;
            acc += __ldg(bv + k) * Wo[k * DD + d2];
        }
        s[tid] = acc;
        __syncthreads();
        if (kh == 0)
            g_cbp[p * DD + d2] = s[d2] + s[128 + d2] + (p == 0 ? bo[d2] : 0.f);
    } else {
        // ------------- misc: S, dq' -------------
        s[tid] = Ws[tid];
        {
            int h = tid >> 5, lane = tid & 31;
            float p = dot4(((const float4*)bk)[h * 32 + lane],
                           ((const float4*)bq)[h * 32 + lane]);
            #pragma unroll
            for (int o = 16; o > 0; o >>= 1)
                p += __shfl_xor_sync(0xffffffffu, p, o);
            if (lane == 0) g_dqs[h] = SCALE * p;
        }
        __syncthreads();
        for (int st = 128; st > 0; st >>= 1) {
            if (tid < st) s[tid] += s[tid + st];
            __syncthreads();
        }
        if (tid == 0) g_S = s[0];
    }
}

// ===========================================================================
// K2: cluster of 4 CTAs per batch, each owns a t-quarter (64 t) and a
// d-quarter (for u) / k-quarter (for out).  grid 256 x 256 thr, dyn smem.
//
// smem float offsets (all 16B-aligned where vector-accessed):
#define SXT_PAD   67
#define OXT   0        // sxT [128 d][67 t]    8576
#define OWS   8576     // Ws quarter           64
#define OXSP  8640     // xs partial           128
#define OXSF  8768     // xs full              128
#define OSU   8896     // u  [d][8 h]          1024
#define OSC   9920     // c[8]                 8
#define OBETA 9928     // beta [64 t][8 h]     512
#define OMAX  10440    // 8
#define OSUM  10448    // 8
#define OSF   10456    // 8
#define OPART 10464    // scratch              2048
#define OYOWN 12512    // y own t-partial      1024
#define OYQ   13536    // y full, own k-quarter 256
#define OOUT  13792    // out partial          128
#define K2_FLOATS 13920

__global__ __launch_bounds__(256) __cluster_dims__(4, 1, 1)
void k_main(const float* __restrict__ x, const float* __restrict__ Ws,
            const float* __restrict__ bs, float* __restrict__ out)
{
    extern __shared__ __align__(16) float sm[];
    float* sxT   = sm + OXT;
    float* sWs   = sm + OWS;
    float* xs_p  = sm + OXSP;
    float* xs_f  = sm + OXSF;
    float* su    = sm + OSU;
    float* sc    = sm + OSC;
    float* sbeta = sm + OBETA;
    float* smax_ = sm + OMAX;
    float* ssum_ = sm + OSUM;
    float* sf    = sm + OSF;
    float* spart = sm + OPART;
    float* syown = sm + OYOWN;
    float* syq   = sm + OYQ;
    float* sout  = sm + OOUT;

    const int tid = threadIdx.x;
    uint32_t rank;
    asm("mov.u32 %0, %%cluster_ctarank;" : "=r"(rank));
    const int r = (int)rank;
    const int b = blockIdx.x >> 2;

    // ---- phase 0: Ws quarter, fill x tile transposed + xs partial ----
    if (tid < 64) sWs[tid] = Ws[r * 64 + tid];
    __syncthreads();
    {
        const int d = tid & 127, tg = tid >> 7;
        const float* xb = x + ((size_t)(b * TT + r * 64)) * DD + d;
        float acc = 0.f;
        #pragma unroll
        for (int k = 0; k < 32; k++) {
            int t = k * 2 + tg;
            float v = xb[t * DD];
            sxT[d * SXT_PAD + t] = v;
            acc += sWs[t] * v;
        }
        spart[tg * 128 + d] = acc;
    }
    __syncthreads();
    if (tid < 128) xs_p[tid] = spart[tid] + spart[128 + tid];
    CLUSTER_SYNC();   // #1

    // ---- phase 1: xs full (all ranks), c[h], u own d-quarter ----
    if (tid < 128) {
        uint32_t la = smem_u32(xs_p + tid);
        float v = 0.f;
        #pragma unroll
        for (int rr = 0; rr < 4; rr++) v += ld_dsmem(mapa_rank(la, rr));
        xs_f[tid] = v;
    }
    __syncthreads();
    {   // c[h]: warp per head (8 warps)
        int h = tid >> 5, lane = tid & 31;
        float p = dot4(((const float4*)xs_f)[lane],
                       ((const float4*)g_gb)[h * 32 + lane]);
        #pragma unroll
        for (int o = 16; o > 0; o >>= 1)
            p += __shfl_xor_sync(0xffffffffu, p, o);
        if (lane == 0) sc[h] = p + g_S * g_dqs[h] + bs[0];
    }
    {   // u[h, d] for d in own quarter
        const int h = tid >> 5, dq = tid & 31;
        const int d = r * 32 + dq;
        const float* Gp = g_G + h * 16384 + d;
        float a0 = g_S * g_ub[h * 128 + d], a1 = 0.f;
        #pragma unroll 8
        for (int dp = 0; dp < 128; dp += 2) {
            a0 += xs_f[dp]     * Gp[dp * 128];
            a1 += xs_f[dp + 1] * Gp[dp * 128 + 128];
        }
        su[d * 8 + h] = a0 + a1;
    }
    CLUSTER_SYNC();   // #2

    // ---- phase 2: gather peers' u quarters; summary over own t-quarter ----
    #pragma unroll
    for (int j = 0; j < 3; j++) {
        int idx = j * 256 + tid;          // 0..767
        int ro = idx >> 8;                // 0..2
        int rr = ro + (ro >= r ? 1 : 0);  // skip own rank
        int off = rr * 256 + (idx & 255); // su offset = d*8+h, d in rr-quarter
        su[off] = ld_dsmem(mapa_rank(smem_u32(su + off), rr));
    }
    __syncthreads();
    {   // thread = (t in 64, g in 2 d-halves, hq in 2 head-quads)
        const int t = tid & 63, gq = tid >> 6;
        const int g = gq & 1, hq = gq >> 1;
        unsigned long long a0 = 0ull, a1 = 0ull;
        #pragma unroll 8
        for (int d = g * 64; d < g * 64 + 64; d++) {
            float xv = sxT[d * SXT_PAD + t];
            unsigned long long xp = pk2(xv, xv);
            const unsigned long long* up =
                (const unsigned long long*)(su + d * 8 + hq * 4);
            ffma2(a0, up[0], xp);
            ffma2(a1, up[1], xp);
        }
        float2 f0 = upk2(a0), f1 = upk2(a1);
        float* pg = spart + g * 512 + t * 8 + hq * 4;
        pg[0] = f0.x; pg[1] = f0.y; pg[2] = f1.x; pg[3] = f1.y;
    }
    __syncthreads();
    #pragma unroll
    for (int k = 0; k < 2; k++) {
        int i = tid + k * 256;            // i = t*8 + h
        sbeta[i] = spart[i] + spart[512 + i] + sc[i & 7];
    }
    __syncthreads();

    // ---- phase 3: own-quarter softmax stats; sbeta <- e^{v-m_own} ----
    {
        int h = tid >> 5, lane = tid & 31;
        float v0 = sbeta[lane * 8 + h];
        float v1 = sbeta[(lane + 32) * 8 + h];
        float m = fmaxf(v0, v1);
        #pragma unroll
        for (int o = 16; o > 0; o >>= 1)
            m = fmaxf(m, __shfl_xor_sync(0xffffffffu, m, o));
        float e0 = __expf(v0 - m), e1 = __expf(v1 - m);
        float ss = e0 + e1;
        #pragma unroll
        for (int o = 16; o > 0; o >>= 1)
            ss += __shfl_xor_sync(0xffffffffu, ss, o);
        sbeta[lane * 8 + h] = e0;
        sbeta[(lane + 32) * 8 + h] = e1;
        if (lane == 0) { smax_[h] = m; ssum_[h] = ss; }
    }
    CLUSTER_SYNC();   // #3
    if (tid < 8) {
        float mo = smax_[tid];
        float M = mo, sums[4], maxs[4];
        #pragma unroll
        for (int rr = 0; rr < 4; rr++) {
            maxs[rr] = ld_dsmem(mapa_rank(smem_u32(smax_ + tid), rr));
            sums[rr] = ld_dsmem(mapa_rank(smem_u32(ssum_ + tid), rr));
            M = fmaxf(M, maxs[rr]);
        }
        float denom = 0.f;
        #pragma unroll
        for (int rr = 0; rr < 4; rr++) denom += sums[rr] * __expf(maxs[rr] - M);
        sf[tid] = __expf(mo - M) / denom;
    }
    __syncthreads();

    // ---- phase 4: y own t-quarter partial (renorm via sf) ----
    {
        const int d = tid & 127, tg = tid >> 7;
        unsigned long long a0 = 0, a1 = 0, a2 = 0, a3 = 0;
        #pragma unroll 8
        for (int t = tg * 32; t < tg * 32 + 32; t++) {
            float xv = sxT[d * SXT_PAD + t];
            unsigned long long xp = pk2(xv, xv);
            const ulonglong2* bp = (const ulonglong2*)(sbeta + t * 8);
            ulonglong2 b01 = bp[0], b23 = bp[1];
            ffma2(a0, b01.x, xp); ffma2(a1, b01.y, xp);
            ffma2(a2, b23.x, xp); ffma2(a3, b23.y, xp);
        }
        float2 v0 = upk2(a0), v1 = upk2(a1), v2 = upk2(a2), v3 = upk2(a3);
        float* pg = spart + tg * 1024;
        pg[0 * 128 + d] = v0.x; pg[1 * 128 + d] = v0.y;
        pg[2 * 128 + d] = v1.x; pg[3 * 128 + d] = v1.y;
        pg[4 * 128 + d] = v2.x; pg[5 * 128 + d] = v2.y;
        pg[6 * 128 + d] = v3.x; pg[7 * 128 + d] = v3.y;
    }
    __syncthreads();
    #pragma unroll
    for (int k = 0; k < 4; k++) {
        int i = tid + k * 256;            // i = k-index = h*128 + d
        syown[i] = sf[i >> 7] * (spart[i] + spart[1024 + i]);
    }
    CLUSTER_SYNC();   // #4

    // ---- phase 5: y full for own k-quarter; out partial over it ----
    {
        int k = r * 256 + tid;
        uint32_t la = smem_u32(syown + k);
        float v = 0.f;
        #pragma unroll
        for (int rr = 0; rr < 4; rr++) v += ld_dsmem(mapa_rank(la, rr));
        syq[tid] = v;
    }
    __syncthreads();
    {
        const int d2 = tid & 127, kg = tid >> 7;
        const float* Mp = g_M + (r * 256) * 128 + d2;
        float acc = 0.f;
        #pragma unroll 8
        for (int kk = 0; kk < 128; kk++) {
            int kl = kg * 128 + kk;
            acc += syq[kl] * Mp[kl * 128];
        }
        spart[kg * 128 + d2] = acc;
    }
    __syncthreads();
    if (tid < 128) sout[tid] = spart[tid] + spart[128 + tid];
    CLUSTER_SYNC();   // #5
    if (tid < 32) {
        int d2 = r * 32 + tid;
        float o = 0.f;
        #pragma unroll
        for (int p = 0; p < 8; p++) o += g_cbp[p * DD + d2];
        uint32_t la = smem_u32(sout + d2);
        #pragma unroll
        for (int rr = 0; rr < 4; rr++) o += ld_dsmem(mapa_rank(la, rr));
        out[b * DD + d2] = o;
    }
    CLUSTER_SYNC();   // #6: no CTA exits while peers may read its smem
}

// ===========================================================================
extern "C" void kernel_launch(void* const* d_in, const int* in_sizes, int n_in,
                              void* d_out, int out_size) {
    const float* x  = (const float*)d_in[0];
    const float* Wq = (const float*)d_in[1];
    const float* bq = (const float*)d_in[2];
    const float* Wk = (const float*)d_in[3];
    const float* bk = (const float*)d_in[4];
    const float* Wv = (const float*)d_in[5];
    const float* bv = (const float*)d_in[6];
    const float* Ws = (const float*)d_in[7];
    const float* bs = (const float*)d_in[8];
    const float* Wo = (const float*)d_in[9];
    const float* bo = (const float*)d_in[10];
    float* out = (float*)d_out;

    static bool attr_done = false;
    if (!attr_done) {
        cudaFuncSetAttribute(k_main, cudaFuncAttributeMaxDynamicSharedMemorySize,
                             K2_FLOATS * 4);
        attr_done = true;
    }

    k_pre<<<145, 256>>>(Ws, Wk, bk, Wq, bq, Wv, bv, Wo, bo);
    k_main<<<256, 256, K2_FLOATS * 4>>>(x, Ws, bs, out);
}

// round 8
// speedup vs baseline: 2.1429x; 1.3117x over previous
#include <cuda_runtime.h>
#include <cstdint>

// Temporal_Attention — weight-space-collapsed.
// k_pre: weight-only precompute (G', ub', gb', dq', M, cbias, S).
// k_main: per-batch cluster of 4 CTAs (t-quarters); fused xs/u/summary/softmax/
//         y/out with DSMEM exchanges; float4 G/M loads, register-cached x rows.
// B=64, T=256, D=128, H=8, E=128.  out[B,D] fp32.

#define BB 64
#define TT 256
#define DD 128
#define HH 8
#define HE 1024
#define SCALE 0.088388347648318447f

static __device__ float g_S;
static __device__ __align__(16) float g_G[HH * DD * DD];   // [h][dp][d]
static __device__ __align__(16) float g_ub[HH * DD];
static __device__ __align__(16) float g_gb[HH * DD];
static __device__ float g_dqs[HH];
static __device__ __align__(16) float g_M[HE * DD];        // [k][d2]
static __device__ __align__(16) float g_cbp[8 * DD];

// ---- helpers ---------------------------------------------------------------
__device__ __forceinline__ void ffma2(unsigned long long& d,
                                      unsigned long long a, unsigned long long b) {
    asm("fma.rn.f32x2 %0, %1, %2, %0;" : "+l"(d) : "l"(a), "l"(b));
}
__device__ __forceinline__ unsigned long long pk2(float x, float y) {
    unsigned long long r;
    asm("mov.b64 %0, {%1, %2};" : "=l"(r) : "f"(x), "f"(y));
    return r;
}
__device__ __forceinline__ float2 upk2(unsigned long long v) {
    float lo, hi;
    asm("mov.b64 {%0, %1}, %2;" : "=f"(lo), "=f"(hi) : "l"(v));
    return make_float2(lo, hi);
}
__device__ __forceinline__ float dot4(float4 a, float4 b) {
    return a.x * b.x + a.y * b.y + a.z * b.z + a.w * b.w;
}
__device__ __forceinline__ uint32_t smem_u32(const void* p) {
    uint32_t a;
    asm("{ .reg .u64 t; cvta.to.shared.u64 t, %1; cvt.u32.u64 %0, t; }"
        : "=r"(a) : "l"(p));
    return a;
}
__device__ __forceinline__ uint32_t mapa_rank(uint32_t addr, uint32_t rank) {
    uint32_t r;
    asm("mapa.shared::cluster.u32 %0, %1, %2;" : "=r"(r) : "r"(addr), "r"(rank));
    return r;
}
__device__ __forceinline__ float ld_dsmem(uint32_t a) {
    float v;
    asm volatile("ld.shared::cluster.f32 %0, [%1];" : "=f"(v) : "r"(a));
    return v;
}
#define CLUSTER_SYNC() do { \
    asm volatile("barrier.cluster.arrive.aligned;" ::: "memory"); \
    asm volatile("barrier.cluster.wait.aligned;" ::: "memory"); \
} while (0)
#define CLUSTER_ARRIVE() asm volatile("barrier.cluster.arrive.aligned;" ::: "memory")
#define CLUSTER_WAIT()   asm volatile("barrier.cluster.wait.aligned;" ::: "memory")

// ===========================================================================
// K1: grid 145 x 256.  roles: G(0-63) | M(64-127) | gb(128-135)
//                             | cbias(136-143) | misc(144)
__global__ __launch_bounds__(256) void k_pre(
    const float* __restrict__ Ws,
    const float* __restrict__ Wk, const float* __restrict__ bk,
    const float* __restrict__ Wq, const float* __restrict__ bq,
    const float* __restrict__ Wv, const float* __restrict__ bv,
    const float* __restrict__ Wo, const float* __restrict__ bo)
{
    __shared__ __align__(16) float s[12288];   // 48 KB
    const int blk = blockIdx.x, tid = threadIdx.x;

    if (blk < 64) {
        // ------------- G role: G'[h, r0..r0+15, :] (+ub on rt==0) -------------
        const int w = blk, h = w >> 3, rt = w & 7, r0 = rt * 16;
        const int d2 = tid & 127, rg = tid >> 7;
        float4* wq4s = (float4*)s;            // [128][17] float4
        float4* wk4s = (float4*)(s + 8704);   // [16][16]
        float4* bk4s = (float4*)(s + 9728);   // [16]
        const float4* Wq4 = (const float4*)Wq;
        const float4* Wk4 = (const float4*)Wk;
        float acc[8];
        #pragma unroll
        for (int j = 0; j < 8; j++) acc[j] = 0.f;
        float ubacc = 0.f;
        for (int e0 = 0; e0 < 2; e0++) {           // e-chunks of 64
            #pragma unroll
            for (int k = 0; k < 8; k++) {
                int i = tid + k * 256;
                int dd = i >> 4, eq = i & 15;
                wq4s[dd * 17 + eq] = Wq4[dd * 256 + h * 32 + e0 * 16 + eq];
            }
            {
                int r = tid >> 4, eq = tid & 15;
                wk4s[r * 16 + eq] = Wk4[(r0 + r) * 256 + h * 32 + e0 * 16 + eq];
            }
            if (rt == 0 && tid < 16)
                bk4s[tid] = ((const float4*)bk)[h * 32 + e0 * 16 + tid];
            __syncthreads();
            #pragma unroll 4
            for (int e4 = 0; e4 < 16; e4++) {
                float4 q4 = wq4s[d2 * 17 + e4];
                #pragma unroll
                for (int j = 0; j < 8; j++)
                    acc[j] += dot4(q4, wk4s[(rg * 8 + j) * 16 + e4]);
                if (rt == 0 && rg == 0) ubacc += dot4(q4, bk4s[e4]);
            }
            __syncthreads();
        }
        #pragma unroll
        for (int j = 0; j < 8; j++)
            g_G[h * 16384 + (r0 + rg * 8 + j) * DD + d2] = SCALE * acc[j];
        if (rt == 0 && rg == 0) g_ub[h * DD + d2] = SCALE * ubacc;
    } else if (blk < 128) {
        // ------------- M role: M[h, r0..r0+15, :] -------------
        const int w = blk - 64, h = w >> 3, r0 = (w & 7) * 16;
        const int d2 = tid & 127, rh = tid >> 7;
        float* wo_s = s;            // 64 x 128
        float* wv_s = s + 8192;     // 16 x 64
        float acc[8];
        #pragma unroll
        for (int j = 0; j < 8; j++) acc[j] = 0.f;
        for (int e0 = 0; e0 < 128; e0 += 64) {
            for (int i = tid; i < 8192; i += 256) {
                int e = i >> 7, dd = i & 127;
                wo_s[i] = Wo[(h * 128 + e0 + e) * DD + dd];
            }
            for (int i = tid; i < 1024; i += 256) {
                int r = i >> 6, e = i & 63;
                wv_s[i] = Wv[(r0 + r) * HE + h * 128 + e0 + e];
            }
            __syncthreads();
            #pragma unroll 8
            for (int e = 0; e < 64; e++) {
                float wo = wo_s[e * 128 + d2];
                #pragma unroll
                for (int j = 0; j < 8; j++)
                    acc[j] += wv_s[(rh * 8 + j) * 64 + e] * wo;
            }
            __syncthreads();
        }
        #pragma unroll
        for (int j = 0; j < 8; j++)
            g_M[(h * 128 + r0 + rh * 8 + j) * DD + d2] = acc[j];
    } else if (blk < 136) {
        // ------------- gb role: gb'[h, :] -------------
        const int h = blk - 128, eq = tid & 31, dg = tid >> 5;
        float4 bqv = ((const float4*)bq)[h * 32 + eq];
        const float4* Wk4 = (const float4*)Wk;
        #pragma unroll
        for (int i = 0; i < 16; i++) {
            int dd = dg * 16 + i;
            float p = dot4(Wk4[dd * 256 + h * 32 + eq], bqv);
            #pragma unroll
            for (int o = 16; o > 0; o >>= 1)
                p += __shfl_xor_sync(0xffffffffu, p, o);
            if (eq == 0) g_gb[h * DD + dd] = SCALE * p;
        }
    } else if (blk < 144) {
        // ------------- cbias partial: k-slice p -------------
        const int p = blk - 136, d2 = tid & 127, kh = tid >> 7;
        float acc = 0.f;
        #pragma unroll 8
        for (int i = 0; i < 64; i++) {
            int k = p * 128 + kh * 64 + i;
            acc += __ldg(bv + k) * Wo[k * DD + d2];
        }
        s[tid] = acc;
        __syncthreads();
        if (kh == 0)
            g_cbp[p * DD + d2] = s[d2] + s[128 + d2] + (p == 0 ? bo[d2] : 0.f);
    } else {
        // ------------- misc: S, dq' -------------
        s[tid] = Ws[tid];
        {
            int h = tid >> 5, lane = tid & 31;
            float p = dot4(((const float4*)bk)[h * 32 + lane],
                           ((const float4*)bq)[h * 32 + lane]);
            #pragma unroll
            for (int o = 16; o > 0; o >>= 1)
                p += __shfl_xor_sync(0xffffffffu, p, o);
            if (lane == 0) g_dqs[h] = SCALE * p;
        }
        __syncthreads();
        for (int st = 128; st > 0; st >>= 1) {
            if (tid < st) s[tid] += s[tid + st];
            __syncthreads();
        }
        if (tid == 0) g_S = s[0];
    }
}

// ===========================================================================
// K2: cluster of 4 CTAs per batch, each owns a t-quarter (64 t).
//   grid 256 x 256 thr, dynamic smem 55.2 KB.
//
// smem float offsets:
#define SX_PAD  132
#define OSX   0        // sx [64 t][132 d pad]   8448
#define OWS   8448     // Ws quarter             64
#define OXSP  8512     // xs partial             128
#define OXSF  8640     // xs full                128
#define OSU   8768     // u  [128 d][8 h]        1024
#define OSC   9792     // c[8]                   8
#define OBETA 9800     // beta [64 t][8 h]       512
#define OMAX  10312    // 8
#define OSUM  10320    // 8
#define OSF   10328    // 8
#define OPART 10336    // scratch                2048
#define OYOWN 12384    // y own t-partial        1024
#define OYQ   13408    // y full, own k-quarter  256
#define OOUT  13664    // out partial            128
#define K2_FLOATS 13792

__global__ __launch_bounds__(256, 2) __cluster_dims__(4, 1, 1)
void k_main(const float* __restrict__ x, const float* __restrict__ Ws,
            const float* __restrict__ bs, float* __restrict__ out)
{
    extern __shared__ __align__(16) float sm[];
    float* sx    = sm + OSX;
    float* sWs   = sm + OWS;
    float* xs_p  = sm + OXSP;
    float* xs_f  = sm + OXSF;
    float* su    = sm + OSU;
    float* sc    = sm + OSC;
    float* sbeta = sm + OBETA;
    float* smax_ = sm + OMAX;
    float* ssum_ = sm + OSUM;
    float* sf    = sm + OSF;
    float* spart = sm + OPART;
    float* syown = sm + OYOWN;
    float* syq   = sm + OYQ;
    float* sout  = sm + OOUT;

    const int tid = threadIdx.x;
    uint32_t rank;
    asm("mov.u32 %0, %%cluster_ctarank;" : "=r"(rank));
    const int r = (int)rank;
    const int b = blockIdx.x >> 2;

    // ---- phase 0: fill x tile [t][d] + xs partial over own t-quarter ----
    if (tid < 64) sWs[tid] = Ws[r * 64 + tid];
    __syncthreads();
    {
        const int d = tid & 127, tg = tid >> 7;
        const float* xb = x + ((size_t)(b * TT + r * 64)) * DD + d;
        float acc = 0.f;
        #pragma unroll
        for (int k = 0; k < 32; k++) {
            int t = k * 2 + tg;
            float v = xb[t * DD];
            sx[t * SX_PAD + d] = v;
            acc += sWs[t] * v;
        }
        spart[tg * 128 + d] = acc;
    }
    __syncthreads();
    if (tid < 128) xs_p[tid] = spart[tid] + spart[128 + tid];
    CLUSTER_SYNC();   // #1

    // ---- phase 1: xs full, u own d-quarter (float4 G loads), c[h] ----
    if (tid < 128) {
        uint32_t la = smem_u32(xs_p + tid);
        float v = 0.f;
        #pragma unroll
        for (int rr = 0; rr < 4; rr++) v += ld_dsmem(mapa_rank(la, rr));
        xs_f[tid] = v;
    }
    __syncthreads();
    {   // u: thread (h = tid>>5; lane: strip = lane>>3 of 4, f4 = lane&7)
        const int h = tid >> 5, lane = tid & 31;
        const int strip = lane >> 3, f4 = lane & 7;
        const float4* G4 = (const float4*)g_G + h * 4096 + r * 8 + f4;
        float4 acc = make_float4(0.f, 0.f, 0.f, 0.f);
        #pragma unroll
        for (int i = 0; i < 32; i++) {
            int dp = strip * 32 + i;
            float xv = xs_f[dp];
            float4 gv = G4[dp * 32];
            acc.x += xv * gv.x; acc.y += xv * gv.y;
            acc.z += xv * gv.z; acc.w += xv * gv.w;
        }
        ((float4*)spart)[(h * 8 + f4) * 4 + strip] = acc;
    }
    __syncthreads();
    {   // reduce strips -> su[d*8+h] (+ S*ub)
        const int h = tid >> 5, f4 = (tid >> 2) & 7, comp = tid & 3;
        const int base = ((h * 8 + f4) * 4) * 4 + comp;
        float v = spart[base] + spart[base + 4] + spart[base + 8] + spart[base + 12];
        const int d = r * 32 + f4 * 4 + comp;
        su[d * 8 + h] = v + g_S * g_ub[h * 128 + d];
    }
    __syncthreads();
    CLUSTER_ARRIVE();   // #2 arrive — peers may read our su once they pass wait
    {   // c[h] computed in the barrier shadow (CTA-local)
        int h = tid >> 5, lane = tid & 31;
        float p = dot4(((const float4*)xs_f)[lane],
                       ((const float4*)g_gb)[h * 32 + lane]);
        #pragma unroll
        for (int o = 16; o > 0; o >>= 1)
            p += __shfl_xor_sync(0xffffffffu, p, o);
        if (lane == 0) sc[h] = p + g_S * g_dqs[h] + bs[0];
    }
    CLUSTER_WAIT();     // #2 wait

    // ---- phase 2: gather peers' u quarters; summary over own t-quarter ----
    #pragma unroll
    for (int j = 0; j < 3; j++) {
        int idx = j * 256 + tid;          // 0..767
        int ro = idx >> 8;                // 0..2
        int rr = ro + (ro >= r ? 1 : 0);  // skip own rank
        int off = rr * 256 + (idx & 255); // su offset = d*8+h, d in rr-quarter
        su[off] = ld_dsmem(mapa_rank(smem_u32(su + off), rr));
    }
    __syncthreads();
    {   // thread = (t = tid&63, dq = tid>>6 of 4): x row cached in registers
        const int t = tid & 63, dq = tid >> 6;
        float xr[32];
        const float4* xrow = (const float4*)(sx + t * SX_PAD + dq * 32);
        #pragma unroll
        for (int i = 0; i < 8; i++) {
            float4 v = xrow[i];
            xr[i * 4 + 0] = v.x; xr[i * 4 + 1] = v.y;
            xr[i * 4 + 2] = v.z; xr[i * 4 + 3] = v.w;
        }
        unsigned long long a0 = 0, a1 = 0, a2 = 0, a3 = 0;
        #pragma unroll
        for (int i = 0; i < 32; i++) {
            int d = dq * 32 + i;
            unsigned long long xp = pk2(xr[i], xr[i]);
            const unsigned long long* up = (const unsigned long long*)(su + d * 8);
            ffma2(a0, up[0], xp); ffma2(a1, up[1], xp);
            ffma2(a2, up[2], xp); ffma2(a3, up[3], xp);
        }
        float2 f0 = upk2(a0), f1 = upk2(a1), f2 = upk2(a2), f3 = upk2(a3);
        ((float4*)spart)[(t * 4 + dq) * 2 + 0] = make_float4(f0.x, f0.y, f1.x, f1.y);
        ((float4*)spart)[(t * 4 + dq) * 2 + 1] = make_float4(f2.x, f2.y, f3.x, f3.y);
    }
    __syncthreads();
    #pragma unroll
    for (int k = 0; k < 2; k++) {
        int i = tid + k * 256;            // i = t*8 + h
        int t = i >> 3, h = i & 7;
        sbeta[i] = spart[(t * 4 + 0) * 8 + h] + spart[(t * 4 + 1) * 8 + h]
                 + spart[(t * 4 + 2) * 8 + h] + spart[(t * 4 + 3) * 8 + h] + sc[h];
    }
    __syncthreads();

    // ---- phase 3: own-quarter softmax stats; sbeta <- e^{v-m_own} ----
    {
        int h = tid >> 5, lane = tid & 31;
        float v0 = sbeta[lane * 8 + h];
        float v1 = sbeta[(lane + 32) * 8 + h];
        float m = fmaxf(v0, v1);
        #pragma unroll
        for (int o = 16; o > 0; o >>= 1)
            m = fmaxf(m, __shfl_xor_sync(0xffffffffu, m, o));
        float e0 = __expf(v0 - m), e1 = __expf(v1 - m);
        float ss = e0 + e1;
        #pragma unroll
        for (int o = 16; o > 0; o >>= 1)
            ss += __shfl_xor_sync(0xffffffffu, ss, o);
        sbeta[lane * 8 + h] = e0;
        sbeta[(lane + 32) * 8 + h] = e1;
        if (lane == 0) { smax_[h] = m; ssum_[h] = ss; }
    }
    CLUSTER_SYNC();   // #3
    if (tid < 8) {
        float mo = smax_[tid];
        float M = mo, sums[4], maxs[4];
        #pragma unroll
        for (int rr = 0; rr < 4; rr++) {
            maxs[rr] = ld_dsmem(mapa_rank(smem_u32(smax_ + tid), rr));
            sums[rr] = ld_dsmem(mapa_rank(smem_u32(ssum_ + tid), rr));
            M = fmaxf(M, maxs[rr]);
        }
        float denom = 0.f;
        #pragma unroll
        for (int rr = 0; rr < 4; rr++) denom += sums[rr] * __expf(maxs[rr] - M);
        sf[tid] = __expf(mo - M) / denom;
    }
    __syncthreads();

    // ---- phase 4: y own t-quarter partial (renorm via sf) ----
    {
        const int d = tid & 127, tg = tid >> 7;
        unsigned long long a0 = 0, a1 = 0, a2 = 0, a3 = 0;
        #pragma unroll 8
        for (int t = tg * 32; t < tg * 32 + 32; t++) {
            float xv = sx[t * SX_PAD + d];
            unsigned long long xp = pk2(xv, xv);
            const ulonglong2* bp = (const ulonglong2*)(sbeta + t * 8);
            ulonglong2 b01 = bp[0], b23 = bp[1];
            ffma2(a0, b01.x, xp); ffma2(a1, b01.y, xp);
            ffma2(a2, b23.x, xp); ffma2(a3, b23.y, xp);
        }
        float2 v0 = upk2(a0), v1 = upk2(a1), v2 = upk2(a2), v3 = upk2(a3);
        float* pg = spart + tg * 1024;
        pg[0 * 128 + d] = v0.x; pg[1 * 128 + d] = v0.y;
        pg[2 * 128 + d] = v1.x; pg[3 * 128 + d] = v1.y;
        pg[4 * 128 + d] = v2.x; pg[5 * 128 + d] = v2.y;
        pg[6 * 128 + d] = v3.x; pg[7 * 128 + d] = v3.y;
    }
    __syncthreads();
    #pragma unroll
    for (int k = 0; k < 4; k++) {
        int i = tid + k * 256;            // i = k-index = h*128 + d
        syown[i] = sf[i >> 7] * (spart[i] + spart[1024 + i]);
    }
    CLUSTER_SYNC();   // #4

    // ---- phase 5: y full for own k-quarter; out partial (float4 M loads) ----
    {
        int k = r * 256 + tid;
        uint32_t la = smem_u32(syown + k);
        float v = 0.f;
        #pragma unroll
        for (int rr = 0; rr < 4; rr++) v += ld_dsmem(mapa_rank(la, rr));
        syq[tid] = v;
    }
    __syncthreads();
    {
        const int kg = tid >> 5, lane = tid & 31;
        const float4* M4 = (const float4*)g_M + (r * 256 + kg * 32) * 32 + lane;
        float4 acc = make_float4(0.f, 0.f, 0.f, 0.f);
        #pragma unroll
        for (int kk = 0; kk < 32; kk++) {
            float yk = syq[kg * 32 + kk];
            float4 mv = M4[kk * 32];
            acc.x += yk * mv.x; acc.y += yk * mv.y;
            acc.z += yk * mv.z; acc.w += yk * mv.w;
        }
        ((float4*)spart)[kg * 32 + lane] = acc;
    }
    __syncthreads();
    if (tid < 128) {
        float v = 0.f;
        #pragma unroll
        for (int kg = 0; kg < 8; kg++) v += spart[kg * 128 + tid];
        sout[tid] = v;
    }
    CLUSTER_SYNC();   // #5
    if (tid < 32) {
        int d2 = r * 32 + tid;
        float o = 0.f;
        #pragma unroll
        for (int p = 0; p < 8; p++) o += g_cbp[p * DD + d2];
        uint32_t la = smem_u32(sout + d2);
        #pragma unroll
        for (int rr = 0; rr < 4; rr++) o += ld_dsmem(mapa_rank(la, rr));
        out[b * DD + d2] = o;
    }
    CLUSTER_SYNC();   // #6: no CTA exits while peers may read its smem
}

// ===========================================================================
extern "C" void kernel_launch(void* const* d_in, const int* in_sizes, int n_in,
                              void* d_out, int out_size) {
    const float* x  = (const float*)d_in[0];
    const float* Wq = (const float*)d_in[1];
    const float* bq = (const float*)d_in[2];
    const float* Wk = (const float*)d_in[3];
    const float* bk = (const float*)d_in[4];
    const float* Wv = (const float*)d_in[5];
    const float* bv = (const float*)d_in[6];
    const float* Ws = (const float*)d_in[7];
    const float* bs = (const float*)d_in[8];
    const float* Wo = (const float*)d_in[9];
    const float* bo = (const float*)d_in[10];
    float* out = (float*)d_out;

    static bool attr_done = false;
    if (!attr_done) {
        cudaFuncSetAttribute(k_main, cudaFuncAttributeMaxDynamicSharedMemorySize,
                             K2_FLOATS * 4);
        attr_done = true;
    }

    k_pre<<<145, 256>>>(Ws, Wk, bk, Wq, bq, Wv, bv, Wo, bo);
    k_main<<<256, 256, K2_FLOATS * 4>>>(x, Ws, bs, out);
}